// round 1
// baseline (speedup 1.0000x reference)
#include <cuda_runtime.h>
#include <math.h>

#define NMAX    50000
#define DMODEL  128
#define ALPHA   0.2f
#define LN_EPS  1e-5f

// ---------------- scratch (device globals; no allocations allowed) ----------
__device__ __align__(16) float g_Q[NMAX * DMODEL];
__device__ __align__(16) float g_K[NMAX * DMODEL];
__device__ __align__(16) float g_V[NMAX * DMODEL];
__device__ __align__(16) float g_AGG[NMAX * DMODEL];
__device__ int g_is64;

// ---------------- detect edge_index dtype (int32 vs int64) ------------------
// int64 little-endian with values < 2^31 => every odd 32-bit word is 0.
// For int32, odd words are random node ids in [0, N): 64 consecutive zeros is
// impossible in practice.
__global__ void detect_kernel(const unsigned* __restrict__ ei, int E)
{
    if (blockIdx.x == 0 && threadIdx.x == 0) {
        int is64 = 1;
        int m = (E >= 64) ? 64 : E;
        for (int i = 0; i < m; i++) {
            if (ei[2 * i + 1] != 0u) { is64 = 0; break; }
        }
        g_is64 = is64;
    }
}

// ---------------- zero the aggregation buffer -------------------------------
__global__ void zero_kernel(int n4)
{
    float4 z = make_float4(0.f, 0.f, 0.f, 0.f);
    float4* p = reinterpret_cast<float4*>(g_AGG);
    for (int i = blockIdx.x * blockDim.x + threadIdx.x; i < n4;
         i += gridDim.x * blockDim.x)
        p[i] = z;
}

// ---------------- fused QKV projection GEMM ---------------------------------
// Q = x @ Wq^T (scaled by 1/sqrt(HD)), K = x @ Wk^T, V = x @ Wv^T
// Block tile: BM=128 rows x BN=64 output cols, full K=128 in smem.
// 256 threads as 16x16; each thread an 8x4 register tile.
// grid = (nrb, 6): chunks 0-1 -> Q, 2-3 -> K, 4-5 -> V.
#define QKV_SMEM ((128 + 64) * 129 * 4)

__global__ void __launch_bounds__(256, 2)
qkv_kernel(const float* __restrict__ x,
           const float* __restrict__ Wq,
           const float* __restrict__ Wk,
           const float* __restrict__ Wv,
           int n)
{
    extern __shared__ float sm[];
    float* xs = sm;              // [128][129]
    float* ws = sm + 128 * 129;  // [64][129]

    const int chunk = blockIdx.y;         // 0..5
    const int row0  = blockIdx.x * 128;
    const int tid   = threadIdx.x;

    const float* W;
    float* OUT;
    float scale;
    if (chunk < 2)      { W = Wq; OUT = g_Q; scale = 0.25f; }  // 1/sqrt(16)
    else if (chunk < 4) { W = Wk; OUT = g_K; scale = 1.0f; }
    else                { W = Wv; OUT = g_V; scale = 1.0f; }
    const int jbase = (chunk & 1) * 64;

    // load x tile: 128 rows x 32 float4
    for (int t = tid; t < 128 * 32; t += 256) {
        int r  = t >> 5;
        int c4 = t & 31;
        float4 v = make_float4(0.f, 0.f, 0.f, 0.f);
        int gr = row0 + r;
        if (gr < n) v = reinterpret_cast<const float4*>(x)[gr * 32 + c4];
        float* d = xs + r * 129 + c4 * 4;
        d[0] = v.x; d[1] = v.y; d[2] = v.z; d[3] = v.w;
    }
    // load W tile: 64 rows x 32 float4 (W row j is output col jbase+j)
    for (int t = tid; t < 64 * 32; t += 256) {
        int r  = t >> 5;
        int c4 = t & 31;
        float4 v = reinterpret_cast<const float4*>(W)[(jbase + r) * 32 + c4];
        float* d = ws + r * 129 + c4 * 4;
        d[0] = v.x; d[1] = v.y; d[2] = v.z; d[3] = v.w;
    }
    __syncthreads();

    const int ty = tid >> 4;   // 0..15 -> row group
    const int tx = tid & 15;   // 0..15 -> col group
    const int i0 = ty * 8;
    const int j0 = tx * 4;

    float acc[8][4];
#pragma unroll
    for (int u = 0; u < 8; u++)
#pragma unroll
        for (int v = 0; v < 4; v++) acc[u][v] = 0.f;

#pragma unroll 8
    for (int k = 0; k < 128; k++) {
        float b0 = ws[(j0 + 0) * 129 + k];
        float b1 = ws[(j0 + 1) * 129 + k];
        float b2 = ws[(j0 + 2) * 129 + k];
        float b3 = ws[(j0 + 3) * 129 + k];
#pragma unroll
        for (int u = 0; u < 8; u++) {
            float a = xs[(i0 + u) * 129 + k];
            acc[u][0] += a * b0;
            acc[u][1] += a * b1;
            acc[u][2] += a * b2;
            acc[u][3] += a * b3;
        }
    }

#pragma unroll
    for (int u = 0; u < 8; u++) {
        int gr = row0 + i0 + u;
        if (gr < n) {
            float4 o = make_float4(acc[u][0] * scale, acc[u][1] * scale,
                                   acc[u][2] * scale, acc[u][3] * scale);
            reinterpret_cast<float4*>(OUT)[gr * 32 + ((jbase + j0) >> 2)] = o;
        }
    }
}

// ---------------- per-edge attention + scatter-add --------------------------
// One warp per edge. Lane l owns floats [4l..4l+3]; head h = l>>2.
__global__ void __launch_bounds__(256)
edge_kernel(const void* __restrict__ eiv,
            const float* __restrict__ eattr,
            int E)
{
    const int gw   = (blockIdx.x * blockDim.x + threadIdx.x) >> 5;
    const int lane = threadIdx.x & 31;
    if (gw >= E) return;

    int row, col;
    if (g_is64) {
        const long long* ei = reinterpret_cast<const long long*>(eiv);
        row = (int)ei[gw];
        col = (int)ei[(long long)E + gw];
    } else {
        const int* ei = reinterpret_cast<const int*>(eiv);
        row = ei[gw];
        col = ei[E + gw];
    }

    float4 q = reinterpret_cast<const float4*>(g_Q)[row * 32 + lane];  // pre-scaled
    float4 k = reinterpret_cast<const float4*>(g_K)[col * 32 + lane];
    float4 v = reinterpret_cast<const float4*>(g_V)[row * 32 + lane];

    // per-head dot over HD=16 = 4 lanes x float4
    float s = q.x * k.x + q.y * k.y + q.z * k.z + q.w * k.w;
    s += __shfl_xor_sync(0xffffffffu, s, 1);
    s += __shfl_xor_sync(0xffffffffu, s, 2);
    // LeakyReLU
    s = (s > 0.f) ? s : ALPHA * s;

    // edge gate: sigmoid(sum of 16 attrs)
    float ew = 0.f;
    if (lane < 4) {
        float4 a = reinterpret_cast<const float4*>(eattr)[gw * 4 + lane];
        ew = a.x + a.y + a.z + a.w;
    }
    ew += __shfl_xor_sync(0xffffffffu, ew, 1);
    ew += __shfl_xor_sync(0xffffffffu, ew, 2);
    ew = __shfl_sync(0xffffffffu, ew, 0);
    ew = 1.f / (1.f + __expf(-ew));
    s *= ew;

    // softmax across the 8 heads: xor over bits 2..4 hits each head once
    float m = s;
    m = fmaxf(m, __shfl_xor_sync(0xffffffffu, m, 4));
    m = fmaxf(m, __shfl_xor_sync(0xffffffffu, m, 8));
    m = fmaxf(m, __shfl_xor_sync(0xffffffffu, m, 16));
    float p = __expf(s - m);
    float den = p;
    den += __shfl_xor_sync(0xffffffffu, den, 4);
    den += __shfl_xor_sync(0xffffffffu, den, 8);
    den += __shfl_xor_sync(0xffffffffu, den, 16);
    p /= den;

    float* dst = g_AGG + col * DMODEL + lane * 4;
    atomicAdd(dst + 0, p * v.x);
    atomicAdd(dst + 1, p * v.y);
    atomicAdd(dst + 2, p * v.z);
    atomicAdd(dst + 3, p * v.w);
}

// ---------------- output projection + residual + LayerNorm ------------------
// Warp owns 4 rows at a time: out[r] = AGG[r] @ Wo^T + bo + x[r], then LN.
// Smem: Wo transposed [k][j] (float4 per lane) + per-warp agg staging.
#define OUT_SMEM ((128 * 132 + 8 * 4 * 132) * 4)

__global__ void __launch_bounds__(256)
out_ln_kernel(const float* __restrict__ x,
              const float* __restrict__ Wo,
              const float* __restrict__ bo,
              const float* __restrict__ gamma,
              const float* __restrict__ beta,
              float* __restrict__ out,
              int n)
{
    extern __shared__ float sm[];
    float* woT = sm;               // [128][132]  woT[k][j] = Wo[j][k]
    float* ab  = sm + 128 * 132;   // [8 warps][4 rows][132]

    const int tid  = threadIdx.x;
    const int warp = tid >> 5;
    const int lane = tid & 31;

    // load + transpose Wo (one-time; conflicts amortized)
    for (int t = tid; t < 128 * 32; t += 256) {
        int j  = t >> 5;
        int k4 = t & 31;
        float4 v = reinterpret_cast<const float4*>(Wo)[j * 32 + k4];
        woT[(k4 * 4 + 0) * 132 + j] = v.x;
        woT[(k4 * 4 + 1) * 132 + j] = v.y;
        woT[(k4 * 4 + 2) * 132 + j] = v.z;
        woT[(k4 * 4 + 3) * 132 + j] = v.w;
    }
    __syncthreads();

    float4 bo4 = reinterpret_cast<const float4*>(bo)[lane];
    float4 g4  = reinterpret_cast<const float4*>(gamma)[lane];
    float4 b4  = reinterpret_cast<const float4*>(beta)[lane];

    float* my = ab + warp * 4 * 132;
    const int warp_stride = gridDim.x * 8 * 4;

    for (int r0 = (blockIdx.x * 8 + warp) * 4; r0 < n; r0 += warp_stride) {
        // stage 4 agg rows
#pragma unroll
        for (int r = 0; r < 4; r++) {
            int gr = r0 + r;
            float4 v = make_float4(0.f, 0.f, 0.f, 0.f);
            if (gr < n) v = reinterpret_cast<const float4*>(g_AGG)[gr * 32 + lane];
            reinterpret_cast<float4*>(my + r * 132)[lane] = v;
        }
        __syncwarp();

        float acc[4][4];
#pragma unroll
        for (int r = 0; r < 4; r++)
#pragma unroll
            for (int u = 0; u < 4; u++) acc[r][u] = 0.f;

#pragma unroll 8
        for (int k = 0; k < 128; k++) {
            float4 w = reinterpret_cast<const float4*>(woT + k * 132)[lane];
#pragma unroll
            for (int r = 0; r < 4; r++) {
                float a = my[r * 132 + k];
                acc[r][0] += a * w.x;
                acc[r][1] += a * w.y;
                acc[r][2] += a * w.z;
                acc[r][3] += a * w.w;
            }
        }

#pragma unroll
        for (int r = 0; r < 4; r++) {
            int gr = r0 + r;
            if (gr >= n) break;
            float4 xv = reinterpret_cast<const float4*>(x)[gr * 32 + lane];
            float o0 = acc[r][0] + bo4.x + xv.x;
            float o1 = acc[r][1] + bo4.y + xv.y;
            float o2 = acc[r][2] + bo4.z + xv.z;
            float o3 = acc[r][3] + bo4.w + xv.w;

            float s  = o0 + o1 + o2 + o3;
            float ss = o0 * o0 + o1 * o1 + o2 * o2 + o3 * o3;
#pragma unroll
            for (int off = 16; off >= 1; off >>= 1) {
                s  += __shfl_xor_sync(0xffffffffu, s,  off);
                ss += __shfl_xor_sync(0xffffffffu, ss, off);
            }
            float mu  = s * (1.f / 128.f);
            float var = ss * (1.f / 128.f) - mu * mu;
            float inv = rsqrtf(var + LN_EPS);

            float4 o;
            o.x = (o0 - mu) * inv * g4.x + b4.x;
            o.y = (o1 - mu) * inv * g4.y + b4.y;
            o.z = (o2 - mu) * inv * g4.z + b4.z;
            o.w = (o3 - mu) * inv * g4.w + b4.w;
            reinterpret_cast<float4*>(out)[gr * 32 + lane] = o;
        }
        __syncwarp();
    }
}

// ---------------- launcher ---------------------------------------------------
extern "C" void kernel_launch(void* const* d_in, const int* in_sizes, int n_in,
                              void* d_out, int out_size)
{
    const float* x     = (const float*)d_in[0];
    const void*  ei    = d_in[1];
    const float* eattr = (const float*)d_in[2];
    const float* Wq    = (const float*)d_in[3];
    const float* Wk    = (const float*)d_in[4];
    const float* Wv    = (const float*)d_in[5];
    const float* Wo    = (const float*)d_in[6];
    const float* bo    = (const float*)d_in[7];
    const float* gamma = (const float*)d_in[8];
    const float* beta  = (const float*)d_in[9];
    float* out = (float*)d_out;

    int n = in_sizes[0] / DMODEL;
    int E = in_sizes[1] / 2;
    if (n > NMAX) n = NMAX;

    cudaFuncSetAttribute(qkv_kernel,
                         cudaFuncAttributeMaxDynamicSharedMemorySize, QKV_SMEM);
    cudaFuncSetAttribute(out_ln_kernel,
                         cudaFuncAttributeMaxDynamicSharedMemorySize, OUT_SMEM);

    detect_kernel<<<1, 32>>>((const unsigned*)ei, E);
    zero_kernel<<<512, 256>>>(n * 32);

    int nrb = (n + 127) / 128;
    qkv_kernel<<<dim3(nrb, 6), 256, QKV_SMEM>>>(x, Wq, Wk, Wv, n);

    long long ethreads = (long long)E * 32;
    int eblocks = (int)((ethreads + 255) / 256);
    edge_kernel<<<eblocks, 256>>>(ei, eattr, E);

    out_ln_kernel<<<296, 256, OUT_SMEM>>>(x, Wo, bo, gamma, beta, out, n);
}

// round 2
// speedup vs baseline: 1.0722x; 1.0722x over previous
#include <cuda_runtime.h>
#include <math.h>

#define NMAX    50000
#define DMODEL  128
#define ALPHA   0.2f
#define LN_EPS  1e-5f

// ---------------- scratch (device globals; no allocations allowed) ----------
__device__ __align__(16) float g_Q[NMAX * DMODEL];
__device__ __align__(16) float g_K[NMAX * DMODEL];
__device__ __align__(16) float g_V[NMAX * DMODEL];
__device__ __align__(16) float g_AGG[NMAX * DMODEL];
__device__ int g_is64;

// ---------------- detect edge_index dtype (int32 vs int64) ------------------
__global__ void detect_kernel(const unsigned* __restrict__ ei, int E)
{
    if (blockIdx.x == 0 && threadIdx.x == 0) {
        int is64 = 1;
        int m = (E >= 64) ? 64 : E;
        for (int i = 0; i < m; i++) {
            if (ei[2 * i + 1] != 0u) { is64 = 0; break; }
        }
        g_is64 = is64;
    }
}

// ---------------- zero the aggregation buffer -------------------------------
__global__ void zero_kernel(int n4)
{
    float4 z = make_float4(0.f, 0.f, 0.f, 0.f);
    float4* p = reinterpret_cast<float4*>(g_AGG);
    for (int i = blockIdx.x * blockDim.x + threadIdx.x; i < n4;
         i += gridDim.x * blockDim.x)
        p[i] = z;
}

// ---------------- fused QKV projection GEMM ---------------------------------
// One block = 128 rows of x, loaded to smem ONCE, then looped over Wq/Wk/Wv.
// 256 threads; thread tile 8x8 with interleaved cols j = tx + 16*v
// (conflict-free b reads: tx*129 mod 32 = tx).
#define QKV_SMEM (2 * 128 * 129 * 4)

__global__ void __launch_bounds__(256, 1)
qkv_kernel(const float* __restrict__ x,
           const float* __restrict__ Wq,
           const float* __restrict__ Wk,
           const float* __restrict__ Wv,
           int n)
{
    extern __shared__ float sm[];
    float* xs = sm;              // [128][129]
    float* ws = sm + 128 * 129;  // [128][129]

    const int row0 = blockIdx.x * 128;
    const int tid  = threadIdx.x;
    const int ty   = tid >> 4;   // 0..15
    const int tx   = tid & 15;   // 0..15
    const int i0   = ty * 8;

    // load x tile once: 128 rows x 32 float4
    for (int t = tid; t < 128 * 32; t += 256) {
        int r  = t >> 5;
        int c4 = t & 31;
        float4 v = make_float4(0.f, 0.f, 0.f, 0.f);
        int gr = row0 + r;
        if (gr < n) v = reinterpret_cast<const float4*>(x)[gr * 32 + c4];
        float* d = xs + r * 129 + c4 * 4;
        d[0] = v.x; d[1] = v.y; d[2] = v.z; d[3] = v.w;
    }

    const float* Ws[3] = {Wq, Wk, Wv};
    float* Os[3]       = {g_Q, g_K, g_V};

    for (int w = 0; w < 3; w++) {
        __syncthreads();   // xs ready (w=0) / previous compute done with ws
        const float* W = Ws[w];
        for (int t = tid; t < 128 * 32; t += 256) {
            int r  = t >> 5;
            int c4 = t & 31;
            float4 v = reinterpret_cast<const float4*>(W)[r * 32 + c4];
            float* d = ws + r * 129 + c4 * 4;
            d[0] = v.x; d[1] = v.y; d[2] = v.z; d[3] = v.w;
        }
        __syncthreads();

        float acc[8][8];
#pragma unroll
        for (int u = 0; u < 8; u++)
#pragma unroll
            for (int v = 0; v < 8; v++) acc[u][v] = 0.f;

#pragma unroll 8
        for (int k = 0; k < 128; k++) {
            float a_[8], b_[8];
#pragma unroll
            for (int u = 0; u < 8; u++) a_[u] = xs[(i0 + u) * 129 + k];
#pragma unroll
            for (int v = 0; v < 8; v++) b_[v] = ws[(tx + 16 * v) * 129 + k];
#pragma unroll
            for (int u = 0; u < 8; u++)
#pragma unroll
                for (int v = 0; v < 8; v++)
                    acc[u][v] += a_[u] * b_[v];
        }

        const float scale = (w == 0) ? 0.25f : 1.0f;  // fold 1/sqrt(HD) into Q
        float* OUT = Os[w];
#pragma unroll
        for (int u = 0; u < 8; u++) {
            int gr = row0 + i0 + u;
            if (gr < n) {
#pragma unroll
                for (int v = 0; v < 8; v++)
                    OUT[gr * DMODEL + tx + 16 * v] = acc[u][v] * scale;
            }
        }
    }
}

// ---------------- per-edge attention + scatter-add --------------------------
// One warp per edge. Lane l owns floats [4l..4l+3]; head h = l>>2.
__global__ void __launch_bounds__(256)
edge_kernel(const void* __restrict__ eiv,
            const float* __restrict__ eattr,
            int E)
{
    const int gw   = (blockIdx.x * blockDim.x + threadIdx.x) >> 5;
    const int lane = threadIdx.x & 31;
    if (gw >= E) return;

    int row, col;
    if (g_is64) {
        const long long* ei = reinterpret_cast<const long long*>(eiv);
        row = (int)ei[gw];
        col = (int)ei[(long long)E + gw];
    } else {
        const int* ei = reinterpret_cast<const int*>(eiv);
        row = ei[gw];
        col = ei[E + gw];
    }

    float4 q = reinterpret_cast<const float4*>(g_Q)[row * 32 + lane];  // pre-scaled
    float4 k = reinterpret_cast<const float4*>(g_K)[col * 32 + lane];
    float4 v = reinterpret_cast<const float4*>(g_V)[row * 32 + lane];

    // per-head dot over HD=16 = 4 lanes x float4
    float s = q.x * k.x + q.y * k.y + q.z * k.z + q.w * k.w;
    s += __shfl_xor_sync(0xffffffffu, s, 1);
    s += __shfl_xor_sync(0xffffffffu, s, 2);
    // LeakyReLU
    s = (s > 0.f) ? s : ALPHA * s;

    // edge gate: sigmoid(sum of 16 attrs)
    float ew = 0.f;
    if (lane < 4) {
        float4 a = reinterpret_cast<const float4*>(eattr)[gw * 4 + lane];
        ew = a.x + a.y + a.z + a.w;
    }
    ew += __shfl_xor_sync(0xffffffffu, ew, 1);
    ew += __shfl_xor_sync(0xffffffffu, ew, 2);
    ew = __shfl_sync(0xffffffffu, ew, 0);
    ew = 1.f / (1.f + __expf(-ew));
    s *= ew;

    // softmax across the 8 heads: xor over bits 2..4 hits each head once
    float m = s;
    m = fmaxf(m, __shfl_xor_sync(0xffffffffu, m, 4));
    m = fmaxf(m, __shfl_xor_sync(0xffffffffu, m, 8));
    m = fmaxf(m, __shfl_xor_sync(0xffffffffu, m, 16));
    float p = __expf(s - m);
    float den = p;
    den += __shfl_xor_sync(0xffffffffu, den, 4);
    den += __shfl_xor_sync(0xffffffffu, den, 8);
    den += __shfl_xor_sync(0xffffffffu, den, 16);
    p /= den;

    // single vector reduction instead of 4 scalar atomics
    float* dst = g_AGG + col * DMODEL + lane * 4;
    asm volatile("red.global.add.v4.f32 [%0], {%1, %2, %3, %4};"
                 :: "l"(dst), "f"(p * v.x), "f"(p * v.y),
                    "f"(p * v.z), "f"(p * v.w)
                 : "memory");
}

// ---------------- output projection + residual + LayerNorm ------------------
// Block-level GEMM (AGG @ Wo^T) with 8x8 thread tiles, epilogue staged to
// stride-132 smem, then warps do residual + LN with conflict-free float4 reads.
#define OUT_SMEM ((2 * 128 * 129 + 128 * 132) * 4)

__global__ void __launch_bounds__(256, 1)
out_ln_kernel(const float* __restrict__ x,
              const float* __restrict__ Wo,
              const float* __restrict__ bo,
              const float* __restrict__ gamma,
              const float* __restrict__ beta,
              float* __restrict__ out,
              int n)
{
    extern __shared__ float sm[];
    float* as  = sm;                  // [128][129]  AGG tile
    float* ws  = sm + 128 * 129;      // [128][129]  Wo
    float* res = sm + 2 * 128 * 129;  // [128][132]  GEMM result staging

    const int row0 = blockIdx.x * 128;
    const int tid  = threadIdx.x;
    const int ty   = tid >> 4;
    const int tx   = tid & 15;
    const int i0   = ty * 8;

    for (int t = tid; t < 128 * 32; t += 256) {
        int r  = t >> 5;
        int c4 = t & 31;
        float4 v = make_float4(0.f, 0.f, 0.f, 0.f);
        int gr = row0 + r;
        if (gr < n) v = reinterpret_cast<const float4*>(g_AGG)[gr * 32 + c4];
        float* d = as + r * 129 + c4 * 4;
        d[0] = v.x; d[1] = v.y; d[2] = v.z; d[3] = v.w;
    }
    for (int t = tid; t < 128 * 32; t += 256) {
        int r  = t >> 5;
        int c4 = t & 31;
        float4 v = reinterpret_cast<const float4*>(Wo)[r * 32 + c4];
        float* d = ws + r * 129 + c4 * 4;
        d[0] = v.x; d[1] = v.y; d[2] = v.z; d[3] = v.w;
    }
    __syncthreads();

    float acc[8][8];
#pragma unroll
    for (int u = 0; u < 8; u++)
#pragma unroll
        for (int v = 0; v < 8; v++) acc[u][v] = 0.f;

#pragma unroll 8
    for (int k = 0; k < 128; k++) {
        float a_[8], b_[8];
#pragma unroll
        for (int u = 0; u < 8; u++) a_[u] = as[(i0 + u) * 129 + k];
#pragma unroll
        for (int v = 0; v < 8; v++) b_[v] = ws[(tx + 16 * v) * 129 + k];
#pragma unroll
        for (int u = 0; u < 8; u++)
#pragma unroll
            for (int v = 0; v < 8; v++)
                acc[u][v] += a_[u] * b_[v];
    }

    // stage to smem
#pragma unroll
    for (int u = 0; u < 8; u++)
#pragma unroll
        for (int v = 0; v < 8; v++)
            res[(i0 + u) * 132 + tx + 16 * v] = acc[u][v];
    __syncthreads();

    // residual + LayerNorm: 8 warps x 16 rows each
    const int warp = tid >> 5;
    const int lane = tid & 31;
    float4 bo4 = reinterpret_cast<const float4*>(bo)[lane];
    float4 g4  = reinterpret_cast<const float4*>(gamma)[lane];
    float4 b4  = reinterpret_cast<const float4*>(beta)[lane];

    for (int r = warp; r < 128; r += 8) {
        int gr = row0 + r;
        if (gr >= n) continue;
        float4 a  = *reinterpret_cast<float4*>(res + r * 132 + lane * 4);
        float4 xv = reinterpret_cast<const float4*>(x)[gr * 32 + lane];
        float o0 = a.x + bo4.x + xv.x;
        float o1 = a.y + bo4.y + xv.y;
        float o2 = a.z + bo4.z + xv.z;
        float o3 = a.w + bo4.w + xv.w;

        float s  = o0 + o1 + o2 + o3;
        float ss = o0 * o0 + o1 * o1 + o2 * o2 + o3 * o3;
#pragma unroll
        for (int off = 16; off >= 1; off >>= 1) {
            s  += __shfl_xor_sync(0xffffffffu, s,  off);
            ss += __shfl_xor_sync(0xffffffffu, ss, off);
        }
        float mu  = s * (1.f / 128.f);
        float var = ss * (1.f / 128.f) - mu * mu;
        float inv = rsqrtf(var + LN_EPS);

        float4 o;
        o.x = (o0 - mu) * inv * g4.x + b4.x;
        o.y = (o1 - mu) * inv * g4.y + b4.y;
        o.z = (o2 - mu) * inv * g4.z + b4.z;
        o.w = (o3 - mu) * inv * g4.w + b4.w;
        reinterpret_cast<float4*>(out)[gr * 32 + lane] = o;
    }
}

// ---------------- launcher ---------------------------------------------------
extern "C" void kernel_launch(void* const* d_in, const int* in_sizes, int n_in,
                              void* d_out, int out_size)
{
    const float* x     = (const float*)d_in[0];
    const void*  ei    = d_in[1];
    const float* eattr = (const float*)d_in[2];
    const float* Wq    = (const float*)d_in[3];
    const float* Wk    = (const float*)d_in[4];
    const float* Wv    = (const float*)d_in[5];
    const float* Wo    = (const float*)d_in[6];
    const float* bo    = (const float*)d_in[7];
    const float* gamma = (const float*)d_in[8];
    const float* beta  = (const float*)d_in[9];
    float* out = (float*)d_out;

    int n = in_sizes[0] / DMODEL;
    int E = in_sizes[1] / 2;
    if (n > NMAX) n = NMAX;

    cudaFuncSetAttribute(qkv_kernel,
                         cudaFuncAttributeMaxDynamicSharedMemorySize, QKV_SMEM);
    cudaFuncSetAttribute(out_ln_kernel,
                         cudaFuncAttributeMaxDynamicSharedMemorySize, OUT_SMEM);

    detect_kernel<<<1, 32>>>((const unsigned*)ei, E);
    zero_kernel<<<512, 256>>>(n * 32);

    int nrb = (n + 127) / 128;
    qkv_kernel<<<nrb, 256, QKV_SMEM>>>(x, Wq, Wk, Wv, n);

    long long ethreads = (long long)E * 32;
    int eblocks = (int)((ethreads + 255) / 256);
    edge_kernel<<<eblocks, 256>>>(ei, eattr, E);

    out_ln_kernel<<<nrb, 256, OUT_SMEM>>>(x, Wo, bo, gamma, beta, out, n);
}